// round 3
// baseline (speedup 1.0000x reference)
#include <cuda_runtime.h>
#include <cstdint>
#include <math.h>

#define FULLMASK 0xffffffffu

// Problem constants
#define NB   256   // batch
#define NV   512   // num vars
#define NE   32    // embed dim
#define NIN  512   // in dim
#define NK   10    // top-k

// Scratch (device globals — no allocation allowed)
__device__ float g_c2[NB * NE];
__device__ float g_gate[NB];

// ---------------- packed f32x2 helpers (ptxas won't auto-fuse; PTX only) ----
__device__ __forceinline__ unsigned long long mul2(unsigned long long a,
                                                   unsigned long long b) {
    unsigned long long r;
    asm("mul.rn.f32x2 %0, %1, %2;" : "=l"(r) : "l"(a), "l"(b));
    return r;
}
__device__ __forceinline__ unsigned long long fma2(unsigned long long a,
                                                   unsigned long long b,
                                                   unsigned long long c) {
    unsigned long long r;
    asm("fma.rn.f32x2 %0, %1, %2, %3;" : "=l"(r) : "l"(a), "l"(b), "l"(c));
    return r;
}
__device__ __forceinline__ float hsum2(unsigned long long a) {
    float lo, hi;
    asm("mov.b64 {%0,%1}, %2;" : "=f"(lo), "=f"(hi) : "l"(a));
    return lo + hi;
}

// ---------------- Kernel 1: context MLP -> c2[b,e], gate[b] -----------------
// grid = 256 (one block per batch), block = 128
__global__ void mlp_kernel(const float* __restrict__ ctx,
                           const float* __restrict__ W1,
                           const float* __restrict__ b1,
                           const float* __restrict__ W2,
                           const float* __restrict__ b2,
                           const float* __restrict__ Wg,
                           const float* __restrict__ bg) {
    __shared__ float x_sh[NIN];
    __shared__ float h_sh[NE];
    int b   = blockIdx.x;
    int tid = threadIdx.x;

    // stage x[b] (512 floats) via float4
    ((float4*)x_sh)[tid] = ((const float4*)(ctx + b * NIN))[tid];
    __syncthreads();

    // h[e] = relu(x . W1[e,:] + b1[e]); 4 threads per output e
    int e = tid >> 2, p = tid & 3;
    const float4* wrow = (const float4*)(W1 + e * NIN + p * 128);
    const float4* xrow = (const float4*)(x_sh + p * 128);
    float acc = 0.f;
#pragma unroll
    for (int q = 0; q < 32; ++q) {
        float4 wv = wrow[q];
        float4 xv = xrow[q];
        acc += wv.x * xv.x + wv.y * xv.y + wv.z * xv.z + wv.w * xv.w;
    }
    acc += __shfl_xor_sync(FULLMASK, acc, 1);
    acc += __shfl_xor_sync(FULLMASK, acc, 2);
    if (p == 0) h_sh[e] = fmaxf(acc + b1[e], 0.f);
    __syncthreads();

    // c[e'] = h . W2[e',:] + b2[e'];  c2 = c*c;  gate = sigmoid(c . Wg + bg)
    if (tid < NE) {
        float cv = b2[tid];
#pragma unroll
        for (int f = 0; f < NE; ++f) cv += h_sh[f] * W2[tid * NE + f];
        g_c2[b * NE + tid] = cv * cv;
        float gp = cv * Wg[tid];
#pragma unroll
        for (int o = 16; o; o >>= 1) gp += __shfl_xor_sync(FULLMASK, gp, o);
        if (tid == 0) g_gate[b] = 1.f / (1.f + expf(-(gp + bg[0])));
    }
}

// ---------------- Kernel 2: scores + top-k mask + sigmoid + gate ------------
// grid = 2048 (8 blocks per batch, 64 rows each), block = 256 (8 warps)
// One warp per row i: lane owns j = k*32+lane for k in [0,16).
// emb is staged in smem, 128B/row, float4-slot XOR swizzle (q ^ (j&7)) so
// LDS.128 with lanes on consecutive rows is bank-conflict free.
__global__ void adj_kernel(const float* __restrict__ emb,
                           float* __restrict__ out) {
    extern __shared__ char smem_raw[];
    __shared__ float4 c2s4[8];
    __shared__ float  gate_s;

    int tid  = threadIdx.x;
    int lane = tid & 31;
    int w    = tid >> 5;
    int b    = blockIdx.x >> 3;
    int ibase = (blockIdx.x & 7) << 6;

    // stage emb (512 rows x 8 float4), swizzled
    const float4* eg = (const float4*)emb;
    float4* es = (float4*)smem_raw;
#pragma unroll
    for (int t = 0; t < 16; ++t) {
        int idx = tid + (t << 8);
        int j = idx >> 3, q = idx & 7;
        es[(j << 3) | (q ^ (j & 7))] = eg[idx];
    }
    if (tid < 8)  c2s4[tid] = ((const float4*)(g_c2 + (b << 5)))[tid];
    if (tid == 0) gate_s = g_gate[b];
    __syncthreads();

    float gate = gate_s;
    const char* smem_b = smem_raw;
    const ulonglong2* c2p = (const ulonglong2*)c2s4;

    // per-thread constant swizzle offsets (j&7 == lane&7 for j = k*32+lane)
    const int jsw = lane & 7;
    int joff[8];
#pragma unroll
    for (int q = 0; q < 8; ++q) joff[q] = ((q ^ jsw) << 4);

    for (int t = 0; t < 8; ++t) {
        int i = ibase + (w << 3) + t;

        // zi[e] = c2[e] * emb[i,e]   (packed as 16 f32x2)
        unsigned long long zi[16];
        {
            int isw = i & 7;
            const char* irow = smem_b + (i << 7);
#pragma unroll
            for (int q = 0; q < 8; ++q) {
                ulonglong2 ev = *(const ulonglong2*)(irow + ((q ^ isw) << 4));
                ulonglong2 cv = c2p[q];
                zi[2 * q]     = mul2(ev.x, cv.x);
                zi[2 * q + 1] = mul2(ev.y, cv.y);
            }
        }

        // scores for this lane's 16 columns
        float sc[16];
#pragma unroll
        for (int k = 0; k < 16; ++k) {
            const char* jrow = smem_b + ((size_t)((k << 5) | lane) << 7);
            unsigned long long a0 = 0ull, a1 = 0ull;
#pragma unroll
            for (int q = 0; q < 8; ++q) {
                ulonglong2 ev = *(const ulonglong2*)(jrow + joff[q]);
                a0 = fma2(ev.x, zi[2 * q],     a0);
                a1 = fma2(ev.y, zi[2 * q + 1], a1);
            }
            sc[k] = hsum2(a0) + hsum2(a1);
        }

        // 10th-largest of the 512 row scores (warp-cooperative extraction).
        // Each round: warp max m; owning lane(s) re-scan keeping only values < m.
        const float NEGF = -3.402823466e38f;
        float lmax = sc[0];
#pragma unroll
        for (int k = 1; k < 16; ++k) lmax = fmaxf(lmax, sc[k]);
        float m = lmax;
#pragma unroll 1
        for (int r = 0; r < NK; ++r) {
            m = lmax;
#pragma unroll
            for (int o = 16; o; o >>= 1)
                m = fmaxf(m, __shfl_xor_sync(FULLMASK, m, o));
            if (r == NK - 1) break;
            if (lmax == m) {
                float nm = NEGF;
#pragma unroll
                for (int k = 0; k < 16; ++k) {
                    float tv = sc[k];
                    nm = fmaxf(nm, (tv < m) ? tv : NEGF);
                }
                lmax = nm;
            }
        }
        float thr = m;

        // masked sigmoid * gate; sigmoid only for kept (~10/row) entries
        float* orow = out + (((size_t)(b << 9) + (size_t)i) << 9);
#pragma unroll
        for (int k = 0; k < 16; ++k) {
            float s = sc[k];
            float v = 0.0f;
            if (s >= thr) v = gate / (1.0f + expf(-s));
            orow[(k << 5) | lane] = v;  // fully coalesced: j = k*32 + lane
        }
    }
}

// ---------------------------------------------------------------------------
extern "C" void kernel_launch(void* const* d_in, const int* in_sizes, int n_in,
                              void* d_out, int out_size) {
    const float* ctx = (const float*)d_in[0];  // context_vec [256,512]
    const float* emb = (const float*)d_in[1];  // var_emb     [512,32]
    const float* W1  = (const float*)d_in[2];  // [32,512]
    const float* b1  = (const float*)d_in[3];  // [32]
    const float* W2  = (const float*)d_in[4];  // [32,32]
    const float* b2  = (const float*)d_in[5];  // [32]
    const float* Wg  = (const float*)d_in[6];  // [1,32]
    const float* bg  = (const float*)d_in[7];  // [1]
    float* out = (float*)d_out;

    cudaFuncSetAttribute(adj_kernel,
                         cudaFuncAttributeMaxDynamicSharedMemorySize, 65536);

    mlp_kernel<<<256, 128>>>(ctx, W1, b1, W2, b2, Wg, bg);
    adj_kernel<<<2048, 256, 65536>>>(emb, out);
}